// round 11
// baseline (speedup 1.0000x reference)
#include <cuda_runtime.h>
#include <cstdint>

#define H 128
#define NB 3
#define SEQ 2048
#define G4 512

__device__ float g_pre[NB * SEQ * G4];
__device__ float g_ys1[NB * SEQ * H];
__device__ float g_WT2[128 * G4];
__device__ float g_a2[NB * H];
__device__ float g_bb2[NB * H];

__device__ __forceinline__ float sigm(float x) {
    return __fdividef(1.0f, 1.0f + __expf(-x));
}
__device__ __forceinline__ float tanh_fast(float x) {
    return 2.0f * __fdividef(1.0f, 1.0f + __expf(-2.0f * x)) - 1.0f;
}
__device__ __forceinline__ unsigned int smem_u32(const void* p) {
    unsigned int a;
    asm("{ .reg .u64 t; cvta.to.shared.u64 t, %1; cvt.u32.u64 %0, t; }" : "=r"(a) : "l"(p));
    return a;
}

// grid 4: 0..2 BN1+pre1 per branch; 3 pack Wih2^T
__global__ void __launch_bounds__(512) k_prep(
    const float* __restrict__ x,
    const float* __restrict__ g1, const float* __restrict__ b1,
    const float* __restrict__ Wih1,
    const float* __restrict__ bih1, const float* __restrict__ bhh1,
    const float* __restrict__ Wih2)
{
    const int bx = blockIdx.x, tid = threadIdx.x;
    if (bx == 3) {
        for (int i = tid; i < 128 * G4; i += 512) {
            int k = i >> 9, r = i & 511;
            g_WT2[i] = Wih2[r * 128 + k];
        }
        return;
    }
    __shared__ float a1[16], bb1[16];
    const int w = tid >> 5, lane = tid & 31;
    {
        float s = 0.f, sq = 0.f;
        for (int m = lane; m < 384; m += 32) {
            int n = m / 3, d = m - 3 * n;
            float v = x[(n * 48 + bx * 16 + w) * 3 + d];
            s += v; sq += v * v;
        }
        #pragma unroll
        for (int o = 16; o; o >>= 1) {
            s  += __shfl_xor_sync(0xffffffffu, s, o);
            sq += __shfl_xor_sync(0xffffffffu, sq, o);
        }
        if (lane == 0) {
            float mean = s * (1.0f / 384.0f);
            float var  = sq * (1.0f / 384.0f) - mean * mean;
            float a = g1[w] * rsqrtf(var + 1e-5f);
            a1[w] = a; bb1[w] = b1[w] - mean * a;
        }
    }
    __syncthreads();
    const int r = tid;
    const float w0 = Wih1[r * 3], w1 = Wih1[r * 3 + 1], w2 = Wih1[r * 3 + 2];
    const float bias = bih1[r] + bhh1[r];
    float* pre = g_pre + bx * (SEQ * G4);
    #pragma unroll 4
    for (int s = 0; s < SEQ; s++) {
        int n = s & 127, t = s >> 7;
        const float* xp = x + (n * 48 + bx * 16 + t) * 3;
        float a = a1[t], bb = bb1[t];
        float x0 = fmaf(xp[0], a, bb);
        float x1 = fmaf(xp[1], a, bb);
        float x2 = fmaf(xp[2], a, bb);
        pre[s * G4 + r] = bias + w0 * x0 + w1 * x1 + w2 * x2;
    }
}

// M-split cluster pair per branch: CTA q owns h-units [64q,64q+64) and computes
// their full 256 gate rows. 2 threads/row: warps 0-7 dot over own-h K-half,
// warps 8-15 over peer-h K-half (mbar-guarded). Exchange = 64 floats/step.
__global__ void __launch_bounds__(512, 1) __cluster_dims__(2, 1, 1)
k_scan2(const float* __restrict__ Whh,
        const float* __restrict__ h0s, const float* __restrict__ c0s,
        float* __restrict__ dout, int layer)
{
    const int tid = threadIdx.x;
    const int lane = tid & 31;
    unsigned int q;
    asm("mov.u32 %0, %%cluster_ctarank;" : "=r"(q));
    const int b = blockIdx.x >> 1;

    const int idx = tid & 255;          // gate row within CTA: g*64 + ul
    const int g = idx >> 6;
    const int ul = idx & 63;
    const int grow = g * 128 + 64 * (int)q + ul;    // global gate row
    const int half = tid >> 8;          // 0: own-h K-half, 1: peer-h K-half
    const int kbase = half == 0 ? 64 * (int)q : 64 * (1 - (int)q);

    __shared__ __align__(16) float sh_hO[64];       // own h (current)
    __shared__ __align__(16) float sh_hin[2][64];   // peer h, slotted
    __shared__ float sh_part[256];
    __shared__ float sh_act[256];
    __shared__ __align__(8) unsigned long long mbar[2];

    const unsigned int mb_l  = smem_u32(&mbar[0]);
    const unsigned int hin_l = smem_u32(&sh_hin[0][0]);
    unsigned int mb_r, hin_r;
    asm("mapa.shared::cluster.u32 %0, %1, %2;" : "=r"(mb_r)  : "r"(mb_l),  "r"(q ^ 1u));
    asm("mapa.shared::cluster.u32 %0, %1, %2;" : "=r"(hin_r) : "r"(hin_l), "r"(q ^ 1u));

    if (tid == 0) {
        asm volatile("mbarrier.init.shared.b64 [%0], %1;" :: "r"(mb_l), "r"(2u) : "memory");
        asm volatile("mbarrier.init.shared.b64 [%0], %1;" :: "r"(mb_l + 8u), "r"(2u) : "memory");
    }

    // 64 weights per thread (row grow, k in [kbase, kbase+64)), packed as f32x2
    unsigned long long w[32];
    {
        const ulonglong2* wp = (const ulonglong2*)(Whh + grow * 128 + kbase);
        #pragma unroll
        for (int j = 0; j < 16; j++) { ulonglong2 t = wp[j]; w[2 * j] = t.x; w[2 * j + 1] = t.y; }
    }

    float c = 0.f;
    if (tid < 64) {
        sh_hO[tid] = h0s[(2 * b + layer) * H + 64 * q + tid];
        c          = c0s[(2 * b + layer) * H + 64 * q + tid];
    } else if (tid < 128) {
        int u = tid - 64;   // preload peer half of h0 (no exchange at s=0)
        sh_hin[0][u] = h0s[(2 * b + layer) * H + 64 * (1 - (int)q) + u];
    }
    const float* __restrict__ pre = g_pre + b * (SEQ * G4);
    float* __restrict__ ob = layer ? (dout + b * (SEQ * H)) : (g_ys1 + b * (SEQ * H));

    float pcur = (half == 0) ? pre[grow] : 0.f;

    // cluster-wide: mbar init + initial smem state visible
    asm volatile("barrier.cluster.arrive.aligned;" ::: "memory");
    asm volatile("barrier.cluster.wait.aligned;" ::: "memory");

    for (int s = 0; s < SEQ; s++) {
        // peer-half warps wait for peer h of step s (pushed at end of peer's s-1)
        if (half == 1 && s > 0) {
            unsigned int mba = mb_l + (unsigned)(s & 1) * 8u;
            unsigned int par = (unsigned)(((s - 1) >> 1) & 1);
            unsigned int done = 0;
            while (!done) {
                asm volatile(
                    "{\n\t.reg .pred p;\n\t"
                    "mbarrier.try_wait.parity.acquire.cluster.shared::cta.b64 p, [%1], %2, 0x989680;\n\t"
                    "selp.b32 %0, 1, 0, p;\n\t}"
                    : "=r"(done) : "r"(mba), "r"(par) : "memory");
            }
        }

        const ulonglong2* hp = (half == 0) ? (const ulonglong2*)sh_hO
                                           : (const ulonglong2*)sh_hin[s & 1];
        unsigned long long a0 = 0ull, a1 = 0ull;
        #pragma unroll
        for (int j = 0; j < 16; j++) {
            ulonglong2 h2 = hp[j];
            asm("fma.rn.f32x2 %0, %1, %2, %0;" : "+l"(a0) : "l"(w[2 * j]),     "l"(h2.x));
            asm("fma.rn.f32x2 %0, %1, %2, %0;" : "+l"(a1) : "l"(w[2 * j + 1]), "l"(h2.y));
        }
        float s00 = __uint_as_float((unsigned)a0);
        float s01 = __uint_as_float((unsigned)(a0 >> 32));
        float s10 = __uint_as_float((unsigned)a1);
        float s11 = __uint_as_float((unsigned)(a1 >> 32));
        float acc = (s00 + s01) + (s10 + s11);

        if (half == 1) sh_part[idx] = acc;
        __syncthreads();                       // partials ready

        if (half == 0) {
            float gval = acc + sh_part[idx] + pcur;
            sh_act[idx] = (g == 2) ? tanh_fast(gval) : sigm(gval);
            int snext = (s + 1 < SEQ) ? s + 1 : s;
            pcur = pre[snext * G4 + grow];     // prefetch; latency hidden
        }
        __syncthreads();                       // activations ready

        if (tid < 64) {
            float ig = sh_act[tid];
            float fg = sh_act[64 + tid];
            float gg = sh_act[128 + tid];
            float og = sh_act[192 + tid];
            c = fg * c + ig * gg;
            float h = og * tanh_fast(c);
            sh_hO[tid] = h;
            ob[s * H + 64 * q + tid] = h;
            // push h to peer's receive slot for step s+1 (skip at final step:
            // an unconsumed in-flight remote store at CTA exit traps)
            if (s + 1 < SEQ) {
                asm volatile("st.shared::cluster.f32 [%0], %1;"
                             :: "r"(hin_r + (unsigned)((s + 1) & 1) * 256u + (unsigned)tid * 4u),
                                "f"(h) : "memory");
                __syncwarp();
                if (lane == 0) {
                    asm volatile("mbarrier.arrive.release.cluster.shared::cluster.b64 _, [%0];"
                                 :: "r"(mb_r + (unsigned)((s + 1) & 1) * 8u) : "memory");
                }
            }
        }
        __syncthreads();                       // sh_hO / buffers safe for next step
    }

    // no CTA exits while any peer-targeted traffic could be in flight
    asm volatile("barrier.cluster.arrive.aligned;" ::: "memory");
    asm volatile("barrier.cluster.wait.aligned;" ::: "memory");
}

__global__ void __launch_bounds__(512) k_bn2(
    const float* __restrict__ g2, const float* __restrict__ b2)
{
    const int b = blockIdx.x, w = threadIdx.x >> 5, lane = threadIdx.x & 31;
    const float* ys = g_ys1 + b * (SEQ * H);
    for (int ch = w; ch < H; ch += 16) {
        float s = 0.f, sq = 0.f;
        for (int m = lane; m < 2048; m += 32) {
            int a = m >> 7, l = m & 127;
            float v = ys[(a * 128 + ch) * H + l];
            s += v; sq += v * v;
        }
        #pragma unroll
        for (int o = 16; o; o >>= 1) {
            s  += __shfl_xor_sync(0xffffffffu, s, o);
            sq += __shfl_xor_sync(0xffffffffu, sq, o);
        }
        if (lane == 0) {
            float mean = s * (1.0f / 2048.0f);
            float var  = sq * (1.0f / 2048.0f) - mean * mean;
            float a2 = g2[ch] * rsqrtf(var + 1e-5f);
            g_a2[b * H + ch]  = a2;
            g_bb2[b * H + ch] = b2[ch] - mean * a2;
        }
    }
}

__global__ void __launch_bounds__(512) k_pre2(
    const float* __restrict__ bih2, const float* __restrict__ bhh2)
{
    const int b = blockIdx.x >> 6, grp = blockIdx.x & 63, s0 = grp * 32;
    const int tid = threadIdx.x, r = tid;
    __shared__ float sh_x[32][128];
    const float* ys = g_ys1 + b * (SEQ * H);
    for (int i = tid; i < 32 * 128; i += 512) {
        int row = i >> 7, k = i & 127;
        int s2 = s0 + row;
        int ch = s2 >> 4;
        int s1 = ((s2 & 15) << 7) + ch;
        sh_x[row][k] = fmaf(g_a2[b * H + ch], ys[s1 * H + k], g_bb2[b * H + ch]);
    }
    __syncthreads();
    float acc[32];
    #pragma unroll
    for (int i = 0; i < 32; i++) acc[i] = 0.f;
    for (int k = 0; k < 128; k++) {
        float w = g_WT2[k * G4 + r];
        #pragma unroll
        for (int i = 0; i < 32; i++) acc[i] = fmaf(w, sh_x[i][k], acc[i]);
    }
    float bias = bih2[r] + bhh2[r];
    float* pre = g_pre + b * (SEQ * G4);
    #pragma unroll
    for (int i = 0; i < 32; i++) pre[(s0 + i) * G4 + r] = acc[i] + bias;
}

extern "C" void kernel_launch(void* const* d_in, const int* in_sizes, int n_in,
                              void* d_out, int out_size)
{
    const float* x    = (const float*)d_in[0];
    const float* g1   = (const float*)d_in[1];
    const float* b1   = (const float*)d_in[2];
    const float* Wih1 = (const float*)d_in[3];
    const float* Whh1 = (const float*)d_in[4];
    const float* bih1 = (const float*)d_in[5];
    const float* bhh1 = (const float*)d_in[6];
    const float* g2   = (const float*)d_in[7];
    const float* b2   = (const float*)d_in[8];
    const float* Wih2 = (const float*)d_in[9];
    const float* Whh2 = (const float*)d_in[10];
    const float* bih2 = (const float*)d_in[11];
    const float* bhh2 = (const float*)d_in[12];
    const float* h0s  = (const float*)d_in[13];
    const float* c0s  = (const float*)d_in[14];
    float* out = (float*)d_out;

    k_prep<<<4, 512>>>(x, g1, b1, Wih1, bih1, bhh1, Wih2);
    k_scan2<<<NB * 2, 512>>>(Whh1, h0s, c0s, out, 0);
    k_bn2<<<NB, 512>>>(g2, b2);
    k_pre2<<<NB * 64, 512>>>(bih2, bhh2);
    k_scan2<<<NB * 2, 512>>>(Whh2, h0s, c0s, out, 1);
}

// round 13
// speedup vs baseline: 1.5089x; 1.5089x over previous
#include <cuda_runtime.h>
#include <cstdint>

#define H 128
#define NB 3
#define SEQ 2048
#define G4 512

__device__ float g_pre[NB * SEQ * G4];
__device__ float g_ys1[NB * SEQ * H];
__device__ float g_WT2[128 * G4];
__device__ float g_a2[NB * H];
__device__ float g_bb2[NB * H];

__device__ __forceinline__ float sigm(float x) {
    return __fdividef(1.0f, 1.0f + __expf(-x));
}
__device__ __forceinline__ float tanh_fast(float x) {
    return 2.0f * __fdividef(1.0f, 1.0f + __expf(-2.0f * x)) - 1.0f;
}
__device__ __forceinline__ unsigned int smem_u32(const void* p) {
    unsigned int a;
    asm("{ .reg .u64 t; cvta.to.shared.u64 t, %1; cvt.u32.u64 %0, t; }" : "=r"(a) : "l"(p));
    return a;
}
__device__ __forceinline__ void mbar_wait(unsigned int mba, unsigned int par) {
    unsigned int done = 0;
    while (!done) {
        asm volatile(
            "{\n\t.reg .pred p;\n\t"
            "mbarrier.try_wait.parity.acquire.cluster.shared::cta.b64 p, [%1], %2, 0x989680;\n\t"
            "selp.b32 %0, 1, 0, p;\n\t}"
            : "=r"(done) : "r"(mba), "r"(par) : "memory");
    }
}

// grid 4: 0..2 BN1+pre1 per branch; 3 pack Wih2^T
__global__ void __launch_bounds__(512) k_prep(
    const float* __restrict__ x,
    const float* __restrict__ g1, const float* __restrict__ b1,
    const float* __restrict__ Wih1,
    const float* __restrict__ bih1, const float* __restrict__ bhh1,
    const float* __restrict__ Wih2)
{
    const int bx = blockIdx.x, tid = threadIdx.x;
    if (bx == 3) {
        for (int i = tid; i < 128 * G4; i += 512) {
            int k = i >> 9, r = i & 511;
            g_WT2[i] = Wih2[r * 128 + k];
        }
        return;
    }
    __shared__ float a1[16], bb1[16];
    const int w = tid >> 5, lane = tid & 31;
    {
        float s = 0.f, sq = 0.f;
        for (int m = lane; m < 384; m += 32) {
            int n = m / 3, d = m - 3 * n;
            float v = x[(n * 48 + bx * 16 + w) * 3 + d];
            s += v; sq += v * v;
        }
        #pragma unroll
        for (int o = 16; o; o >>= 1) {
            s  += __shfl_xor_sync(0xffffffffu, s, o);
            sq += __shfl_xor_sync(0xffffffffu, sq, o);
        }
        if (lane == 0) {
            float mean = s * (1.0f / 384.0f);
            float var  = sq * (1.0f / 384.0f) - mean * mean;
            float a = g1[w] * rsqrtf(var + 1e-5f);
            a1[w] = a; bb1[w] = b1[w] - mean * a;
        }
    }
    __syncthreads();
    const int r = tid;
    const float w0 = Wih1[r * 3], w1 = Wih1[r * 3 + 1], w2 = Wih1[r * 3 + 2];
    const float bias = bih1[r] + bhh1[r];
    float* pre = g_pre + bx * (SEQ * G4);
    #pragma unroll 4
    for (int s = 0; s < SEQ; s++) {
        int n = s & 127, t = s >> 7;
        const float* xp = x + (n * 48 + bx * 16 + t) * 3;
        float a = a1[t], bb = bb1[t];
        float x0 = fmaf(xp[0], a, bb);
        float x1 = fmaf(xp[1], a, bb);
        float x2 = fmaf(xp[2], a, bb);
        pre[s * G4 + r] = bias + w0 * x0 + w1 * x1 + w2 * x2;
    }
}

// Barrier-free M-split: cluster pair per branch, CTA q owns h-units [64q,64q+64).
// 256 threads: tid = u*4 + g  -> full gate row (g*128 + 64q + u), K=128 weights in regs.
// Per step: waitA(own h) -> dot own half -> waitB(peer h) -> dot peer half ->
// act in-register -> 4 shuffles -> c,h (replicated in 4 lanes) -> g==0 publishes h.
__global__ void __launch_bounds__(256, 1) __cluster_dims__(2, 1, 1)
k_scan2(const float* __restrict__ Whh,
        const float* __restrict__ h0s, const float* __restrict__ c0s,
        float* __restrict__ dout, int layer)
{
    const int tid = threadIdx.x;
    const int lane = tid & 31;
    unsigned int q;
    asm("mov.u32 %0, %%cluster_ctarank;" : "=r"(q));
    const int b = blockIdx.x >> 1;

    const int u = tid >> 2;             // h-unit within CTA (0..63)
    const int g = tid & 3;              // gate (i,f,g,o)
    const int row = g * 128 + 64 * (int)q + u;
    const int kO = 64 * (int)q;         // own-h K range base
    const int kP = 64 * (1 - (int)q);   // peer-h K range base

    __shared__ __align__(16) float sh_h[2][H];      // full h, slotted, global-k indexed
    __shared__ __align__(8) unsigned long long mbarA[2];   // own-h ready (8 local arrives)
    __shared__ __align__(8) unsigned long long mbarB[2];   // peer-h ready (8 remote arrives)

    const unsigned int mbA_l = smem_u32(&mbarA[0]);
    const unsigned int mbB_l = smem_u32(&mbarB[0]);
    const unsigned int h_l   = smem_u32(&sh_h[0][0]);
    unsigned int mbB_r, h_r;
    asm("mapa.shared::cluster.u32 %0, %1, %2;" : "=r"(mbB_r) : "r"(mbB_l), "r"(q ^ 1u));
    asm("mapa.shared::cluster.u32 %0, %1, %2;" : "=r"(h_r)   : "r"(h_l),   "r"(q ^ 1u));

    if (tid == 0) {
        asm volatile("mbarrier.init.shared.b64 [%0], %1;" :: "r"(mbA_l), "r"(8u) : "memory");
        asm volatile("mbarrier.init.shared.b64 [%0], %1;" :: "r"(mbA_l + 8u), "r"(8u) : "memory");
        asm volatile("mbarrier.init.shared.b64 [%0], %1;" :: "r"(mbB_l), "r"(8u) : "memory");
        asm volatile("mbarrier.init.shared.b64 [%0], %1;" :: "r"(mbB_l + 8u), "r"(8u) : "memory");
    }

    // weights: full row, packed f32x2; own K-half first, then peer K-half
    unsigned long long wO[32], wP[32];
    {
        const ulonglong2* wpO = (const ulonglong2*)(Whh + row * 128 + kO);
        const ulonglong2* wpP = (const ulonglong2*)(Whh + row * 128 + kP);
        #pragma unroll
        for (int j = 0; j < 16; j++) {
            ulonglong2 t0 = wpO[j]; wO[2 * j] = t0.x; wO[2 * j + 1] = t0.y;
            ulonglong2 t1 = wpP[j]; wP[2 * j] = t1.x; wP[2 * j + 1] = t1.y;
        }
    }

    const float c0 = c0s[(2 * b + layer) * H + 64 * (int)q + u];
    float c = c0;
    if (tid < 128) sh_h[0][tid] = h0s[(2 * b + layer) * H + tid];  // both halves at s=0

    const float* __restrict__ pre = g_pre + b * (SEQ * G4);
    float* __restrict__ ob = layer ? (dout + b * (SEQ * H)) : (g_ys1 + b * (SEQ * H));

    float pcur = pre[row];

    // cluster-wide: mbar init + initial sh_h visible
    asm volatile("barrier.cluster.arrive.aligned;" ::: "memory");
    asm volatile("barrier.cluster.wait.aligned;" ::: "memory");

    for (int s = 0; s < SEQ; s++) {
        const unsigned int slot = (unsigned)(s & 1);
        const unsigned int par  = (unsigned)(((s - 1) >> 1) & 1);

        if (s > 0) mbar_wait(mbA_l + slot * 8u, par);   // own h published

        unsigned long long a0 = 0ull, a1 = 0ull;
        {
            const ulonglong2* hp = (const ulonglong2*)(&sh_h[slot][kO]);
            #pragma unroll
            for (int j = 0; j < 16; j++) {
                ulonglong2 h2 = hp[j];
                asm("fma.rn.f32x2 %0, %1, %2, %0;" : "+l"(a0) : "l"(wO[2 * j]),     "l"(h2.x));
                asm("fma.rn.f32x2 %0, %1, %2, %0;" : "+l"(a1) : "l"(wO[2 * j + 1]), "l"(h2.y));
            }
        }

        if (s > 0) mbar_wait(mbB_l + slot * 8u, par);   // peer h arrived (overlapped)

        unsigned long long a2 = 0ull, a3 = 0ull;
        {
            const ulonglong2* hp = (const ulonglong2*)(&sh_h[slot][kP]);
            #pragma unroll
            for (int j = 0; j < 16; j++) {
                ulonglong2 h2 = hp[j];
                asm("fma.rn.f32x2 %0, %1, %2, %0;" : "+l"(a2) : "l"(wP[2 * j]),     "l"(h2.x));
                asm("fma.rn.f32x2 %0, %1, %2, %0;" : "+l"(a3) : "l"(wP[2 * j + 1]), "l"(h2.y));
            }
        }

        float t0 = __uint_as_float((unsigned)a0) + __uint_as_float((unsigned)(a0 >> 32));
        float t1 = __uint_as_float((unsigned)a1) + __uint_as_float((unsigned)(a1 >> 32));
        float t2 = __uint_as_float((unsigned)a2) + __uint_as_float((unsigned)(a2 >> 32));
        float t3 = __uint_as_float((unsigned)a3) + __uint_as_float((unsigned)(a3 >> 32));
        float gval = pcur + ((t0 + t1) + (t2 + t3));

        float act = (g == 2) ? tanh_fast(gval) : sigm(gval);

        // prefetch next pre (off critical path)
        int snext = (s + 1 < SEQ) ? s + 1 : s;
        pcur = pre[snext * G4 + row];

        // gather the unit's 4 gates (lane group of 4)
        const int base = lane & ~3;
        float ai = __shfl_sync(0xffffffffu, act, base + 0);
        float af = __shfl_sync(0xffffffffu, act, base + 1);
        float ag = __shfl_sync(0xffffffffu, act, base + 2);
        float ao = __shfl_sync(0xffffffffu, act, base + 3);

        c = af * c + ai * ag;
        float h = ao * tanh_fast(c);

        if (g == 0) {
            ob[s * H + 64 * (int)q + u] = h;
            if (s + 1 < SEQ) {
                const unsigned int slot2 = (unsigned)((s + 1) & 1);
                const unsigned int off = slot2 * (H * 4u) + (unsigned)(64 * (int)q + u) * 4u;
                sh_h[slot2][64 * (int)q + u] = h;                       // local own-h
                asm volatile("st.shared::cluster.f32 [%0], %1;"        // peer copy
                             :: "r"(h_r + off), "f"(h) : "memory");
            }
        }
        __syncwarp();
        if (lane == 0 && s + 1 < SEQ) {
            const unsigned int slot2 = (unsigned)((s + 1) & 1);
            asm volatile("mbarrier.arrive.release.cta.shared::cta.b64 _, [%0];"
                         :: "r"(mbA_l + slot2 * 8u) : "memory");
            asm volatile("mbarrier.arrive.release.cluster.shared::cluster.b64 _, [%0];"
                         :: "r"(mbB_r + slot2 * 8u) : "memory");
        }
    }

    // no CTA exits while peer-targeted traffic could be in flight
    asm volatile("barrier.cluster.arrive.aligned;" ::: "memory");
    asm volatile("barrier.cluster.wait.aligned;" ::: "memory");
}

__global__ void __launch_bounds__(512) k_bn2(
    const float* __restrict__ g2, const float* __restrict__ b2)
{
    const int b = blockIdx.x, w = threadIdx.x >> 5, lane = threadIdx.x & 31;
    const float* ys = g_ys1 + b * (SEQ * H);
    for (int ch = w; ch < H; ch += 16) {
        float s = 0.f, sq = 0.f;
        for (int m = lane; m < 2048; m += 32) {
            int a = m >> 7, l = m & 127;
            float v = ys[(a * 128 + ch) * H + l];
            s += v; sq += v * v;
        }
        #pragma unroll
        for (int o = 16; o; o >>= 1) {
            s  += __shfl_xor_sync(0xffffffffu, s, o);
            sq += __shfl_xor_sync(0xffffffffu, sq, o);
        }
        if (lane == 0) {
            float mean = s * (1.0f / 2048.0f);
            float var  = sq * (1.0f / 2048.0f) - mean * mean;
            float a2 = g2[ch] * rsqrtf(var + 1e-5f);
            g_a2[b * H + ch]  = a2;
            g_bb2[b * H + ch] = b2[ch] - mean * a2;
        }
    }
}

__global__ void __launch_bounds__(512) k_pre2(
    const float* __restrict__ bih2, const float* __restrict__ bhh2)
{
    const int b = blockIdx.x >> 6, grp = blockIdx.x & 63, s0 = grp * 32;
    const int tid = threadIdx.x, r = tid;
    __shared__ float sh_x[32][128];
    const float* ys = g_ys1 + b * (SEQ * H);
    for (int i = tid; i < 32 * 128; i += 512) {
        int row = i >> 7, k = i & 127;
        int s2 = s0 + row;
        int ch = s2 >> 4;
        int s1 = ((s2 & 15) << 7) + ch;
        sh_x[row][k] = fmaf(g_a2[b * H + ch], ys[s1 * H + k], g_bb2[b * H + ch]);
    }
    __syncthreads();
    float acc[32];
    #pragma unroll
    for (int i = 0; i < 32; i++) acc[i] = 0.f;
    for (int k = 0; k < 128; k++) {
        float w = g_WT2[k * G4 + r];
        #pragma unroll
        for (int i = 0; i < 32; i++) acc[i] = fmaf(w, sh_x[i][k], acc[i]);
    }
    float bias = bih2[r] + bhh2[r];
    float* pre = g_pre + b * (SEQ * G4);
    #pragma unroll
    for (int i = 0; i < 32; i++) pre[(s0 + i) * G4 + r] = acc[i] + bias;
}

extern "C" void kernel_launch(void* const* d_in, const int* in_sizes, int n_in,
                              void* d_out, int out_size)
{
    const float* x    = (const float*)d_in[0];
    const float* g1   = (const float*)d_in[1];
    const float* b1   = (const float*)d_in[2];
    const float* Wih1 = (const float*)d_in[3];
    const float* Whh1 = (const float*)d_in[4];
    const float* bih1 = (const float*)d_in[5];
    const float* bhh1 = (const float*)d_in[6];
    const float* g2   = (const float*)d_in[7];
    const float* b2   = (const float*)d_in[8];
    const float* Wih2 = (const float*)d_in[9];
    const float* Whh2 = (const float*)d_in[10];
    const float* bih2 = (const float*)d_in[11];
    const float* bhh2 = (const float*)d_in[12];
    const float* h0s  = (const float*)d_in[13];
    const float* c0s  = (const float*)d_in[14];
    float* out = (float*)d_out;

    k_prep<<<4, 512>>>(x, g1, b1, Wih1, bih1, bhh1, Wih2);
    k_scan2<<<NB * 2, 256>>>(Whh1, h0s, c0s, out, 0);
    k_bn2<<<NB, 512>>>(g2, b2);
    k_pre2<<<NB * 64, 512>>>(bih2, bhh2);
    k_scan2<<<NB * 2, 256>>>(Whh2, h0s, c0s, out, 1);
}

// round 14
// speedup vs baseline: 2.4801x; 1.6437x over previous
#include <cuda_runtime.h>
#include <cstdint>

#define H 128
#define NB 3
#define SEQ 2048
#define G4 512

__device__ float g_pre[NB * SEQ * G4];
__device__ float g_ys1[NB * SEQ * H];
__device__ float g_WT2[128 * G4];
__device__ float g_a2[NB * H];
__device__ float g_bb2[NB * H];

__device__ __forceinline__ float sigm(float x) {
    return __fdividef(1.0f, 1.0f + __expf(-x));
}
__device__ __forceinline__ float tanh_fast(float x) {
    return 2.0f * __fdividef(1.0f, 1.0f + __expf(-2.0f * x)) - 1.0f;
}
__device__ __forceinline__ unsigned int smem_u32(const void* p) {
    unsigned int a;
    asm("{ .reg .u64 t; cvta.to.shared.u64 t, %1; cvt.u32.u64 %0, t; }" : "=r"(a) : "l"(p));
    return a;
}
__device__ __forceinline__ void mbar_wait(unsigned int mba, unsigned int par) {
    unsigned int done = 0;
    while (!done) {
        asm volatile(
            "{\n\t.reg .pred p;\n\t"
            "mbarrier.try_wait.parity.acquire.cluster.shared::cta.b64 p, [%1], %2, 0x989680;\n\t"
            "selp.b32 %0, 1, 0, p;\n\t}"
            : "=r"(done) : "r"(mba), "r"(par) : "memory");
    }
}

// grid 4: 0..2 BN1+pre1 per branch; 3 pack Wih2^T
__global__ void __launch_bounds__(512) k_prep(
    const float* __restrict__ x,
    const float* __restrict__ g1, const float* __restrict__ b1,
    const float* __restrict__ Wih1,
    const float* __restrict__ bih1, const float* __restrict__ bhh1,
    const float* __restrict__ Wih2)
{
    const int bx = blockIdx.x, tid = threadIdx.x;
    if (bx == 3) {
        for (int i = tid; i < 128 * G4; i += 512) {
            int k = i >> 9, r = i & 511;
            g_WT2[i] = Wih2[r * 128 + k];
        }
        return;
    }
    __shared__ float a1[16], bb1[16];
    const int w = tid >> 5, lane = tid & 31;
    {
        float s = 0.f, sq = 0.f;
        for (int m = lane; m < 384; m += 32) {
            int n = m / 3, d = m - 3 * n;
            float v = x[(n * 48 + bx * 16 + w) * 3 + d];
            s += v; sq += v * v;
        }
        #pragma unroll
        for (int o = 16; o; o >>= 1) {
            s  += __shfl_xor_sync(0xffffffffu, s, o);
            sq += __shfl_xor_sync(0xffffffffu, sq, o);
        }
        if (lane == 0) {
            float mean = s * (1.0f / 384.0f);
            float var  = sq * (1.0f / 384.0f) - mean * mean;
            float a = g1[w] * rsqrtf(var + 1e-5f);
            a1[w] = a; bb1[w] = b1[w] - mean * a;
        }
    }
    __syncthreads();
    const int r = tid;
    const float w0 = Wih1[r * 3], w1 = Wih1[r * 3 + 1], w2 = Wih1[r * 3 + 2];
    const float bias = bih1[r] + bhh1[r];
    float* pre = g_pre + bx * (SEQ * G4);
    #pragma unroll 4
    for (int s = 0; s < SEQ; s++) {
        int n = s & 127, t = s >> 7;
        const float* xp = x + (n * 48 + bx * 16 + t) * 3;
        float a = a1[t], bb = bb1[t];
        float x0 = fmaf(xp[0], a, bb);
        float x1 = fmaf(xp[1], a, bb);
        float x2 = fmaf(xp[2], a, bb);
        pre[s * G4 + r] = bias + w0 * x0 + w1 * x1 + w2 * x2;
    }
}

// Barrier-free M-split with st.async exchange: cluster pair per branch,
// CTA q owns h-units [64q,64q+64). 256 threads: tid = u*4 + g -> full gate row.
// Peer publish = 64 x st.async (data+tx in ONE fabric crossing); peer-ready
// barrier mbB: 1 local expect_tx arrive + 256 tx bytes per phase.
__global__ void __launch_bounds__(256, 1) __cluster_dims__(2, 1, 1)
k_scan2(const float* __restrict__ Whh,
        const float* __restrict__ h0s, const float* __restrict__ c0s,
        float* __restrict__ dout, int layer)
{
    const int tid = threadIdx.x;
    const int lane = tid & 31;
    unsigned int q;
    asm("mov.u32 %0, %%cluster_ctarank;" : "=r"(q));
    const int b = blockIdx.x >> 1;

    const int u = tid >> 2;             // h-unit within CTA (0..63)
    const int g = tid & 3;              // gate (i,f,g,o)
    const int row = g * 128 + 64 * (int)q + u;
    const int kO = 64 * (int)q;         // own-h K range base
    const int kP = 64 * (1 - (int)q);   // peer-h K range base

    __shared__ __align__(16) float sh_h[2][H];      // full h, slotted, global-k indexed
    __shared__ __align__(8) unsigned long long mbarA[2];   // own-h ready (8 local arrives)
    __shared__ __align__(8) unsigned long long mbarB[2];   // peer-h ready (1 expect_tx + 256B)

    const unsigned int mbA_l = smem_u32(&mbarA[0]);
    const unsigned int mbB_l = smem_u32(&mbarB[0]);
    const unsigned int h_l   = smem_u32(&sh_h[0][0]);
    unsigned int mbB_r, h_r;
    asm("mapa.shared::cluster.u32 %0, %1, %2;" : "=r"(mbB_r) : "r"(mbB_l), "r"(q ^ 1u));
    asm("mapa.shared::cluster.u32 %0, %1, %2;" : "=r"(h_r)   : "r"(h_l),   "r"(q ^ 1u));

    if (tid == 0) {
        asm volatile("mbarrier.init.shared.b64 [%0], %1;" :: "r"(mbA_l), "r"(8u) : "memory");
        asm volatile("mbarrier.init.shared.b64 [%0], %1;" :: "r"(mbA_l + 8u), "r"(8u) : "memory");
        asm volatile("mbarrier.init.shared.b64 [%0], %1;" :: "r"(mbB_l), "r"(1u) : "memory");
        asm volatile("mbarrier.init.shared.b64 [%0], %1;" :: "r"(mbB_l + 8u), "r"(1u) : "memory");
    }

    // weights: full row, packed f32x2; own K-half first, then peer K-half
    unsigned long long wO[32], wP[32];
    {
        const ulonglong2* wpO = (const ulonglong2*)(Whh + row * 128 + kO);
        const ulonglong2* wpP = (const ulonglong2*)(Whh + row * 128 + kP);
        #pragma unroll
        for (int j = 0; j < 16; j++) {
            ulonglong2 t0 = wpO[j]; wO[2 * j] = t0.x; wO[2 * j + 1] = t0.y;
            ulonglong2 t1 = wpP[j]; wP[2 * j] = t1.x; wP[2 * j + 1] = t1.y;
        }
    }

    float c = c0s[(2 * b + layer) * H + 64 * (int)q + u];
    if (tid < 128) sh_h[0][tid] = h0s[(2 * b + layer) * H + tid];  // both halves at s=0

    const float* __restrict__ pre = g_pre + b * (SEQ * G4);
    float* __restrict__ ob = layer ? (dout + b * (SEQ * H)) : (g_ys1 + b * (SEQ * H));

    float pcur = pre[row];

    // cluster-wide: mbar init + initial sh_h visible before any st.async targets them
    asm volatile("barrier.cluster.arrive.aligned;" ::: "memory");
    asm volatile("barrier.cluster.wait.aligned;" ::: "memory");

    for (int s = 0; s < SEQ; s++) {
        const unsigned int slot = (unsigned)(s & 1);
        const unsigned int par  = (unsigned)(((s - 1) >> 1) & 1);

        if (s > 0) mbar_wait(mbA_l + slot * 8u, par);   // own h published

        // arm the NEXT phase's tx expectation (tid0; slot2's prior phase
        // was consumed at step s-1, so re-arming here is race-free)
        if (tid == 0 && s + 1 < SEQ) {
            asm volatile("mbarrier.arrive.expect_tx.shared.b64 _, [%0], %1;"
                         :: "r"(mbB_l + (unsigned)((s + 1) & 1) * 8u), "r"(256u) : "memory");
        }

        unsigned long long a0 = 0ull, a1 = 0ull;
        {
            const ulonglong2* hp = (const ulonglong2*)(&sh_h[slot][kO]);
            #pragma unroll
            for (int j = 0; j < 16; j++) {
                ulonglong2 h2 = hp[j];
                asm("fma.rn.f32x2 %0, %1, %2, %0;" : "+l"(a0) : "l"(wO[2 * j]),     "l"(h2.x));
                asm("fma.rn.f32x2 %0, %1, %2, %0;" : "+l"(a1) : "l"(wO[2 * j + 1]), "l"(h2.y));
            }
        }

        if (s > 0) mbar_wait(mbB_l + slot * 8u, par);   // peer h arrived (overlapped)

        unsigned long long a2 = 0ull, a3 = 0ull;
        {
            const ulonglong2* hp = (const ulonglong2*)(&sh_h[slot][kP]);
            #pragma unroll
            for (int j = 0; j < 16; j++) {
                ulonglong2 h2 = hp[j];
                asm("fma.rn.f32x2 %0, %1, %2, %0;" : "+l"(a2) : "l"(wP[2 * j]),     "l"(h2.x));
                asm("fma.rn.f32x2 %0, %1, %2, %0;" : "+l"(a3) : "l"(wP[2 * j + 1]), "l"(h2.y));
            }
        }

        float t0 = __uint_as_float((unsigned)a0) + __uint_as_float((unsigned)(a0 >> 32));
        float t1 = __uint_as_float((unsigned)a1) + __uint_as_float((unsigned)(a1 >> 32));
        float t2 = __uint_as_float((unsigned)a2) + __uint_as_float((unsigned)(a2 >> 32));
        float t3 = __uint_as_float((unsigned)a3) + __uint_as_float((unsigned)(a3 >> 32));
        float gval = pcur + ((t0 + t1) + (t2 + t3));

        float act = (g == 2) ? tanh_fast(gval) : sigm(gval);

        // prefetch next pre (off critical path)
        int snext = (s + 1 < SEQ) ? s + 1 : s;
        pcur = pre[snext * G4 + row];

        // gather the unit's 4 gates (lane group of 4)
        const int base = lane & ~3;
        float ai = __shfl_sync(0xffffffffu, act, base + 0);
        float af = __shfl_sync(0xffffffffu, act, base + 1);
        float ag = __shfl_sync(0xffffffffu, act, base + 2);
        float ao = __shfl_sync(0xffffffffu, act, base + 3);

        c = af * c + ai * ag;
        float h = ao * tanh_fast(c);

        if (g == 0) {
            ob[s * H + 64 * (int)q + u] = h;
            if (s + 1 < SEQ) {
                const unsigned int slot2 = (unsigned)((s + 1) & 1);
                const unsigned int off = slot2 * (H * 4u) + (unsigned)(64 * (int)q + u) * 4u;
                sh_h[slot2][64 * (int)q + u] = h;           // local own-h
                // peer copy: data + tx-signal in ONE crossing
                asm volatile(
                    "st.async.shared::cluster.mbarrier::complete_tx::bytes.f32 [%0], %1, [%2];"
                    :: "r"(h_r + off), "f"(h), "r"(mbB_r + slot2 * 8u) : "memory");
            }
        }
        __syncwarp();
        if (lane == 0 && s + 1 < SEQ) {
            const unsigned int slot2 = (unsigned)((s + 1) & 1);
            asm volatile("mbarrier.arrive.release.cta.shared::cta.b64 _, [%0];"
                         :: "r"(mbA_l + slot2 * 8u) : "memory");
        }
    }

    // no CTA exits while peer-targeted traffic could be in flight
    asm volatile("barrier.cluster.arrive.aligned;" ::: "memory");
    asm volatile("barrier.cluster.wait.aligned;" ::: "memory");
}

__global__ void __launch_bounds__(512) k_bn2(
    const float* __restrict__ g2, const float* __restrict__ b2)
{
    const int b = blockIdx.x, w = threadIdx.x >> 5, lane = threadIdx.x & 31;
    const float* ys = g_ys1 + b * (SEQ * H);
    for (int ch = w; ch < H; ch += 16) {
        float s = 0.f, sq = 0.f;
        for (int m = lane; m < 2048; m += 32) {
            int a = m >> 7, l = m & 127;
            float v = ys[(a * 128 + ch) * H + l];
            s += v; sq += v * v;
        }
        #pragma unroll
        for (int o = 16; o; o >>= 1) {
            s  += __shfl_xor_sync(0xffffffffu, s, o);
            sq += __shfl_xor_sync(0xffffffffu, sq, o);
        }
        if (lane == 0) {
            float mean = s * (1.0f / 2048.0f);
            float var  = sq * (1.0f / 2048.0f) - mean * mean;
            float a2 = g2[ch] * rsqrtf(var + 1e-5f);
            g_a2[b * H + ch]  = a2;
            g_bb2[b * H + ch] = b2[ch] - mean * a2;
        }
    }
}

__global__ void __launch_bounds__(512) k_pre2(
    const float* __restrict__ bih2, const float* __restrict__ bhh2)
{
    const int b = blockIdx.x >> 6, grp = blockIdx.x & 63, s0 = grp * 32;
    const int tid = threadIdx.x, r = tid;
    __shared__ float sh_x[32][128];
    const float* ys = g_ys1 + b * (SEQ * H);
    for (int i = tid; i < 32 * 128; i += 512) {
        int row = i >> 7, k = i & 127;
        int s2 = s0 + row;
        int ch = s2 >> 4;
        int s1 = ((s2 & 15) << 7) + ch;
        sh_x[row][k] = fmaf(g_a2[b * H + ch], ys[s1 * H + k], g_bb2[b * H + ch]);
    }
    __syncthreads();
    float acc[32];
    #pragma unroll
    for (int i = 0; i < 32; i++) acc[i] = 0.f;
    for (int k = 0; k < 128; k++) {
        float w = g_WT2[k * G4 + r];
        #pragma unroll
        for (int i = 0; i < 32; i++) acc[i] = fmaf(w, sh_x[i][k], acc[i]);
    }
    float bias = bih2[r] + bhh2[r];
    float* pre = g_pre + b * (SEQ * G4);
    #pragma unroll
    for (int i = 0; i < 32; i++) pre[(s0 + i) * G4 + r] = acc[i] + bias;
}

extern "C" void kernel_launch(void* const* d_in, const int* in_sizes, int n_in,
                              void* d_out, int out_size)
{
    const float* x    = (const float*)d_in[0];
    const float* g1   = (const float*)d_in[1];
    const float* b1   = (const float*)d_in[2];
    const float* Wih1 = (const float*)d_in[3];
    const float* Whh1 = (const float*)d_in[4];
    const float* bih1 = (const float*)d_in[5];
    const float* bhh1 = (const float*)d_in[6];
    const float* g2   = (const float*)d_in[7];
    const float* b2   = (const float*)d_in[8];
    const float* Wih2 = (const float*)d_in[9];
    const float* Whh2 = (const float*)d_in[10];
    const float* bih2 = (const float*)d_in[11];
    const float* bhh2 = (const float*)d_in[12];
    const float* h0s  = (const float*)d_in[13];
    const float* c0s  = (const float*)d_in[14];
    float* out = (float*)d_out;

    k_prep<<<4, 512>>>(x, g1, b1, Wih1, bih1, bhh1, Wih2);
    k_scan2<<<NB * 2, 256>>>(Whh1, h0s, c0s, out, 0);
    k_bn2<<<NB, 512>>>(g2, b2);
    k_pre2<<<NB * 64, 512>>>(bih2, bhh2);
    k_scan2<<<NB * 2, 256>>>(Whh2, h0s, c0s, out, 1);
}

// round 15
// speedup vs baseline: 3.2948x; 1.3285x over previous
#include <cuda_runtime.h>
#include <cstdint>

#define H 128
#define NB 3
#define SEQ 2048
#define G4 512
#define CS 4
#define UPC 32

__device__ float g_pre[NB * SEQ * G4];
__device__ float g_ys1[NB * SEQ * H];
__device__ float g_WT2[128 * G4];
__device__ float g_a2[NB * H];
__device__ float g_bb2[NB * H];

__device__ __forceinline__ float sigm(float x) {
    return __fdividef(1.0f, 1.0f + __expf(-x));
}
__device__ __forceinline__ float tanh_fast(float x) {
    return 2.0f * __fdividef(1.0f, 1.0f + __expf(-2.0f * x)) - 1.0f;
}
__device__ __forceinline__ unsigned int smem_u32(const void* p) {
    unsigned int a;
    asm("{ .reg .u64 t; cvta.to.shared.u64 t, %1; cvt.u32.u64 %0, t; }" : "=r"(a) : "l"(p));
    return a;
}
__device__ __forceinline__ void mbar_wait(unsigned int mba, unsigned int par) {
    unsigned int done = 0;
    while (!done) {
        asm volatile(
            "{\n\t.reg .pred p;\n\t"
            "mbarrier.try_wait.parity.acquire.cluster.shared::cta.b64 p, [%1], %2, 0x989680;\n\t"
            "selp.b32 %0, 1, 0, p;\n\t}"
            : "=r"(done) : "r"(mba), "r"(par) : "memory");
    }
}

// grid 4: 0..2 BN1+pre1 per branch; 3 pack Wih2^T
__global__ void __launch_bounds__(512) k_prep(
    const float* __restrict__ x,
    const float* __restrict__ g1, const float* __restrict__ b1,
    const float* __restrict__ Wih1,
    const float* __restrict__ bih1, const float* __restrict__ bhh1,
    const float* __restrict__ Wih2)
{
    const int bx = blockIdx.x, tid = threadIdx.x;
    if (bx == 3) {
        for (int i = tid; i < 128 * G4; i += 512) {
            int k = i >> 9, r = i & 511;
            g_WT2[i] = Wih2[r * 128 + k];
        }
        return;
    }
    __shared__ float a1[16], bb1[16];
    const int w = tid >> 5, lane = tid & 31;
    {
        float s = 0.f, sq = 0.f;
        for (int m = lane; m < 384; m += 32) {
            int n = m / 3, d = m - 3 * n;
            float v = x[(n * 48 + bx * 16 + w) * 3 + d];
            s += v; sq += v * v;
        }
        #pragma unroll
        for (int o = 16; o; o >>= 1) {
            s  += __shfl_xor_sync(0xffffffffu, s, o);
            sq += __shfl_xor_sync(0xffffffffu, sq, o);
        }
        if (lane == 0) {
            float mean = s * (1.0f / 384.0f);
            float var  = sq * (1.0f / 384.0f) - mean * mean;
            float a = g1[w] * rsqrtf(var + 1e-5f);
            a1[w] = a; bb1[w] = b1[w] - mean * a;
        }
    }
    __syncthreads();
    const int r = tid;
    const float w0 = Wih1[r * 3], w1 = Wih1[r * 3 + 1], w2 = Wih1[r * 3 + 2];
    const float bias = bih1[r] + bhh1[r];
    float* pre = g_pre + bx * (SEQ * G4);
    #pragma unroll 4
    for (int s = 0; s < SEQ; s++) {
        int n = s & 127, t = s >> 7;
        const float* xp = x + (n * 48 + bx * 16 + t) * 3;
        float a = a1[t], bb = bb1[t];
        float x0 = fmaf(xp[0], a, bb);
        float x1 = fmaf(xp[1], a, bb);
        float x2 = fmaf(xp[2], a, bb);
        pre[s * G4 + r] = bias + w0 * x0 + w1 * x1 + w2 * x2;
    }
}

// 4-CTA M-split: cluster of 4 per branch, CTA q owns h-units [32q, 32q+32).
// 128 threads: tid = u*4 + g -> full gate row (g*128 + 32q + u), K=128 in regs.
// Local h publish via end-of-step __syncthreads; peer publish via st.async
// (data + tx in one crossing) to 3 peers; mbB[slot] = 1 expect_tx + 384 bytes.
__global__ void __launch_bounds__(128, 1) __cluster_dims__(CS, 1, 1)
k_scan4(const float* __restrict__ Whh,
        const float* __restrict__ h0s, const float* __restrict__ c0s,
        float* __restrict__ dout, int layer)
{
    const int tid = threadIdx.x;
    const int lane = tid & 31;
    unsigned int q;
    asm("mov.u32 %0, %%cluster_ctarank;" : "=r"(q));
    const int b = blockIdx.x >> 2;

    const int u = tid >> 2;               // local unit (0..31)
    const int g = tid & 3;                // gate (i,f,g,o)
    const int uu = UPC * (int)q + u;      // global unit
    const int row = g * 128 + uu;         // global gate row

    __shared__ __align__(16) float sh_h[2][H];
    __shared__ __align__(8) unsigned long long mbarB[2];

    const unsigned int mbB_l = smem_u32(&mbarB[0]);
    const unsigned int h_l   = smem_u32(&sh_h[0][0]);
    unsigned int mbB_r[CS - 1], h_r[CS - 1];
    {
        int pi = 0;
        #pragma unroll
        for (int r = 0; r < CS; r++) {
            if (r != (int)q) {
                asm("mapa.shared::cluster.u32 %0, %1, %2;" : "=r"(mbB_r[pi]) : "r"(mbB_l), "r"((unsigned)r));
                asm("mapa.shared::cluster.u32 %0, %1, %2;" : "=r"(h_r[pi])   : "r"(h_l),   "r"((unsigned)r));
                pi++;
            }
        }
    }

    if (tid == 0) {
        asm volatile("mbarrier.init.shared.b64 [%0], %1;" :: "r"(mbB_l), "r"(1u) : "memory");
        asm volatile("mbarrier.init.shared.b64 [%0], %1;" :: "r"(mbB_l + 8u), "r"(1u) : "memory");
    }

    // full-K weights for this row: 64 f32x2
    unsigned long long w[64];
    {
        const ulonglong2* wp = (const ulonglong2*)(Whh + row * 128);
        #pragma unroll
        for (int j = 0; j < 32; j++) { ulonglong2 t = wp[j]; w[2 * j] = t.x; w[2 * j + 1] = t.y; }
    }

    float c = c0s[(2 * b + layer) * H + uu];
    sh_h[0][tid] = h0s[(2 * b + layer) * H + tid];   // 128 threads: full h0

    const float* __restrict__ pre = g_pre + b * (SEQ * G4);
    float* __restrict__ ob = layer ? (dout + b * (SEQ * H)) : (g_ys1 + b * (SEQ * H));
    float pcur = pre[row];

    // cluster-wide: mbar init + initial sh_h visible before any st.async
    asm volatile("barrier.cluster.arrive.aligned;" ::: "memory");
    asm volatile("barrier.cluster.wait.aligned;" ::: "memory");

    for (int s = 0; s < SEQ; s++) {
        const unsigned int slot = (unsigned)(s & 1);
        const unsigned int par  = (unsigned)(((s - 1) >> 1) & 1);

        // arm next phase's tx expectation (prior phase of slot2 consumed at s-1)
        if (tid == 0 && s + 1 < SEQ) {
            asm volatile("mbarrier.arrive.expect_tx.shared.b64 _, [%0], %1;"
                         :: "r"(mbB_l + (unsigned)((s + 1) & 1) * 8u), "r"((unsigned)(96 * 4)) : "memory");
        }

        if (s > 0) mbar_wait(mbB_l + slot * 8u, par);   // 96 peer floats landed

        // full-K dot, 4 accumulator chains
        unsigned long long a0 = 0ull, a1 = 0ull, a2 = 0ull, a3 = 0ull;
        {
            const ulonglong2* hp = (const ulonglong2*)(&sh_h[slot][0]);  // 32 x (2 f32x2)
            #pragma unroll
            for (int j = 0; j < 16; j++) {
                ulonglong2 ha = hp[2 * j];
                ulonglong2 hb = hp[2 * j + 1];
                asm("fma.rn.f32x2 %0, %1, %2, %0;" : "+l"(a0) : "l"(w[4 * j]),     "l"(ha.x));
                asm("fma.rn.f32x2 %0, %1, %2, %0;" : "+l"(a1) : "l"(w[4 * j + 1]), "l"(ha.y));
                asm("fma.rn.f32x2 %0, %1, %2, %0;" : "+l"(a2) : "l"(w[4 * j + 2]), "l"(hb.x));
                asm("fma.rn.f32x2 %0, %1, %2, %0;" : "+l"(a3) : "l"(w[4 * j + 3]), "l"(hb.y));
            }
        }
        float t0 = __uint_as_float((unsigned)a0) + __uint_as_float((unsigned)(a0 >> 32));
        float t1 = __uint_as_float((unsigned)a1) + __uint_as_float((unsigned)(a1 >> 32));
        float t2 = __uint_as_float((unsigned)a2) + __uint_as_float((unsigned)(a2 >> 32));
        float t3 = __uint_as_float((unsigned)a3) + __uint_as_float((unsigned)(a3 >> 32));
        float gval = pcur + ((t0 + t1) + (t2 + t3));

        float act = (g == 2) ? tanh_fast(gval) : sigm(gval);

        int snext = (s + 1 < SEQ) ? s + 1 : s;
        pcur = pre[snext * G4 + row];          // prefetch, off critical path

        const int base = lane & ~3;
        float ai = __shfl_sync(0xffffffffu, act, base + 0);
        float af = __shfl_sync(0xffffffffu, act, base + 1);
        float ag = __shfl_sync(0xffffffffu, act, base + 2);
        float ao = __shfl_sync(0xffffffffu, act, base + 3);

        c = af * c + ai * ag;
        float h = ao * tanh_fast(c);

        if (g == 0) {
            ob[s * H + uu] = h;
            if (s + 1 < SEQ) {
                const unsigned int slot2 = (unsigned)((s + 1) & 1);
                const unsigned int off = slot2 * (H * 4u) + (unsigned)uu * 4u;
                sh_h[slot2][uu] = h;                          // local copy
                #pragma unroll
                for (int p = 0; p < CS - 1; p++) {
                    asm volatile(
                        "st.async.shared::cluster.mbarrier::complete_tx::bytes.f32 [%0], %1, [%2];"
                        :: "r"(h_r[p] + off), "f"(h), "r"(mbB_r[p] + slot2 * 8u) : "memory");
                }
            }
        }
        __syncthreads();   // local h published; slot buffers safe for next step
    }

    // no CTA exits while peer-targeted traffic could be in flight
    asm volatile("barrier.cluster.arrive.aligned;" ::: "memory");
    asm volatile("barrier.cluster.wait.aligned;" ::: "memory");
}

__global__ void __launch_bounds__(512) k_bn2(
    const float* __restrict__ g2, const float* __restrict__ b2)
{
    const int b = blockIdx.x, w = threadIdx.x >> 5, lane = threadIdx.x & 31;
    const float* ys = g_ys1 + b * (SEQ * H);
    for (int ch = w; ch < H; ch += 16) {
        float s = 0.f, sq = 0.f;
        for (int m = lane; m < 2048; m += 32) {
            int a = m >> 7, l = m & 127;
            float v = ys[(a * 128 + ch) * H + l];
            s += v; sq += v * v;
        }
        #pragma unroll
        for (int o = 16; o; o >>= 1) {
            s  += __shfl_xor_sync(0xffffffffu, s, o);
            sq += __shfl_xor_sync(0xffffffffu, sq, o);
        }
        if (lane == 0) {
            float mean = s * (1.0f / 2048.0f);
            float var  = sq * (1.0f / 2048.0f) - mean * mean;
            float a2 = g2[ch] * rsqrtf(var + 1e-5f);
            g_a2[b * H + ch]  = a2;
            g_bb2[b * H + ch] = b2[ch] - mean * a2;
        }
    }
}

__global__ void __launch_bounds__(512) k_pre2(
    const float* __restrict__ bih2, const float* __restrict__ bhh2)
{
    const int b = blockIdx.x >> 6, grp = blockIdx.x & 63, s0 = grp * 32;
    const int tid = threadIdx.x, r = tid;
    __shared__ float sh_x[32][128];
    const float* ys = g_ys1 + b * (SEQ * H);
    for (int i = tid; i < 32 * 128; i += 512) {
        int row = i >> 7, k = i & 127;
        int s2 = s0 + row;
        int ch = s2 >> 4;
        int s1 = ((s2 & 15) << 7) + ch;
        sh_x[row][k] = fmaf(g_a2[b * H + ch], ys[s1 * H + k], g_bb2[b * H + ch]);
    }
    __syncthreads();
    float acc[32];
    #pragma unroll
    for (int i = 0; i < 32; i++) acc[i] = 0.f;
    for (int k = 0; k < 128; k++) {
        float w = g_WT2[k * G4 + r];
        #pragma unroll
        for (int i = 0; i < 32; i++) acc[i] = fmaf(w, sh_x[i][k], acc[i]);
    }
    float bias = bih2[r] + bhh2[r];
    float* pre = g_pre + b * (SEQ * G4);
    #pragma unroll
    for (int i = 0; i < 32; i++) pre[(s0 + i) * G4 + r] = acc[i] + bias;
}

extern "C" void kernel_launch(void* const* d_in, const int* in_sizes, int n_in,
                              void* d_out, int out_size)
{
    const float* x    = (const float*)d_in[0];
    const float* g1   = (const float*)d_in[1];
    const float* b1   = (const float*)d_in[2];
    const float* Wih1 = (const float*)d_in[3];
    const float* Whh1 = (const float*)d_in[4];
    const float* bih1 = (const float*)d_in[5];
    const float* bhh1 = (const float*)d_in[6];
    const float* g2   = (const float*)d_in[7];
    const float* b2   = (const float*)d_in[8];
    const float* Wih2 = (const float*)d_in[9];
    const float* Whh2 = (const float*)d_in[10];
    const float* bih2 = (const float*)d_in[11];
    const float* bhh2 = (const float*)d_in[12];
    const float* h0s  = (const float*)d_in[13];
    const float* c0s  = (const float*)d_in[14];
    float* out = (float*)d_out;

    k_prep<<<4, 512>>>(x, g1, b1, Wih1, bih1, bhh1, Wih2);
    k_scan4<<<NB * CS, 128>>>(Whh1, h0s, c0s, out, 0);
    k_bn2<<<NB, 512>>>(g2, b2);
    k_pre2<<<NB * 64, 512>>>(bih2, bhh2);
    k_scan4<<<NB * CS, 128>>>(Whh2, h0s, c0s, out, 1);
}